// round 1
// baseline (speedup 1.0000x reference)
#include <cuda_runtime.h>

// bicon_loss: fused sigmoid + bilateral voting + 3 BCE sums -> scalar.
// c_map  f32 [16,8,352,352]
// target f32 [16,1,352,352]
// con    i32 [16,8,352,352]
// out    f32 [1]

#define BB 16
#define HH 352
#define WW 352
#define HW (HH * WW)
#define NPIX (BB * HW)

__device__ double g_acc;

__global__ void zero_acc_kernel() { g_acc = 0.0; }

__global__ void write_out_kernel(float* __restrict__ out) {
    out[0] = (float)g_acc;
}

// SHIFTS[i] = (dx, dy); shifted_i(h,w) = p[7-i](h-dy, w-dx) (0 outside image)
__device__ __constant__ int c_DX[8] = { 1, 0, -1, 1, -1, 1, 0, -1 };
__device__ __constant__ int c_DY[8] = { 1, 1,  1, 0,  0, -1, -1, -1 };

__device__ __forceinline__ float sigmoid_fast(float x) {
    return __fdividef(1.0f, 1.0f + __expf(-x));
}

__global__ void __launch_bounds__(256)
bicon_loss_kernel(const float* __restrict__ c_map,
                  const float* __restrict__ target,
                  const int*   __restrict__ con,
                  int npix)
{
    const float EPSF = 1e-7f;
    const float ONE_M_EPS = 1.0f - 1e-7f;

    int idx = blockIdx.x * blockDim.x + threadIdx.x;
    float local = 0.0f;

    if (idx < npix) {
        int w   = idx % WW;
        int tmp = idx / WW;
        int h   = tmp % HH;
        int b   = tmp / HH;

        const int pixoff = h * WW + w;
        const int cbase  = b * 8 * HW + pixoff;

        float p[8];
        int   t[8];
        #pragma unroll
        for (int c = 0; c < 8; c++) {
            float x = c_map[cbase + c * HW];
            p[c] = sigmoid_fast(x);
            t[c] = con[cbase + c * HW];
        }

        int sum_conn = 0;
        #pragma unroll
        for (int c = 0; c < 8; c++) sum_conn += t[c];
        bool edge = (sum_conn > 0) && (sum_conn < 8);

        float loss_con = 0.0f;
        float loss_bi  = 0.0f;
        float vmax = -1e30f;
        float vmin =  1e30f;

        #pragma unroll
        for (int i = 0; i < 8; i++) {
            int hn = h - c_DY[i];
            int wn = w - c_DX[i];
            float s = 0.0f;
            if ((unsigned)hn < (unsigned)HH && (unsigned)wn < (unsigned)WW) {
                float xn = c_map[(b * 8 + (7 - i)) * HW + hn * WW + wn];
                s = sigmoid_fast(xn);
            }
            float v = p[i] * s;
            vmax = fmaxf(vmax, v);
            vmin = fminf(vmin, v);

            // BCE with binary target collapses to one log per element
            float vc = fminf(fmaxf(v,    EPSF), ONE_M_EPS);
            float pc = fminf(fmaxf(p[i], EPSF), ONE_M_EPS);
            bool tt = (t[i] != 0);
            loss_bi  -= __logf(tt ? vc : (1.0f - vc));
            loss_con -= __logf(tt ? pc : (1.0f - pc));
        }

        // decouple = glo_map*(1-edge) + (1-min)*edge
        float d  = edge ? (1.0f - vmin) : vmax;
        float dc = fminf(fmaxf(d, EPSF), ONE_M_EPS);
        float tg = target[b * HW + pixoff];
        float de = -(tg * __logf(dc) + (1.0f - tg) * __logf(1.0f - dc));

        local = 0.8f * loss_con + de + 0.2f * loss_bi;
    }

    // warp reduce
    #pragma unroll
    for (int o = 16; o > 0; o >>= 1)
        local += __shfl_xor_sync(0xffffffffu, local, o);

    __shared__ float ws[8];
    int lane = threadIdx.x & 31;
    int warp = threadIdx.x >> 5;
    if (lane == 0) ws[warp] = local;
    __syncthreads();

    if (warp == 0) {
        float v = (lane < (int)(blockDim.x >> 5)) ? ws[lane] : 0.0f;
        #pragma unroll
        for (int o = 4; o > 0; o >>= 1)
            v += __shfl_xor_sync(0xffffffffu, v, o);
        if (lane == 0)
            atomicAdd(&g_acc, (double)v);
    }
}

extern "C" void kernel_launch(void* const* d_in, const int* in_sizes, int n_in,
                              void* d_out, int out_size)
{
    const float* c_map  = (const float*)d_in[0];
    const float* target = (const float*)d_in[1];
    const int*   con    = (const int*)  d_in[2];
    float* out = (float*)d_out;

    zero_acc_kernel<<<1, 1>>>();

    int threads = 256;
    int blocks  = (NPIX + threads - 1) / threads;
    bicon_loss_kernel<<<blocks, threads>>>(c_map, target, con, NPIX);

    write_out_kernel<<<1, 1>>>(out);
}